// round 9
// baseline (speedup 1.0000x reference)
#include <cuda_runtime.h>
#include <cuda_fp16.h>

#define BB   256
#define TT   512
#define HH   128
#define G4   512
#define IND  10
#define TRG  32

typedef unsigned long long u64;

// ---------------- packed f32x2 helpers ----------------
__device__ __forceinline__ void ffma2(u64& acc, u64 a, u64 b) {
    asm("fma.rn.f32x2 %0, %1, %2, %0;" : "+l"(acc) : "l"(a), "l"(b));
}
__device__ __forceinline__ u64 pk(float lo, float hi) {
    u64 d; asm("mov.b64 %0, {%1, %2};" : "=l"(d) : "f"(lo), "f"(hi)); return d;
}
__device__ __forceinline__ float psum(u64 a) {
    float x, y; asm("mov.b64 {%0, %1}, %2;" : "=f"(x), "=f"(y) : "l"(a));
    return x + y;
}
__device__ __forceinline__ u64 h2u64(unsigned int h2bits) {
    __half2 h = *reinterpret_cast<__half2*>(&h2bits);
    float2 f = __half22float2(h);
    u64 d; asm("mov.b64 %0, {%1, %2};" : "=l"(d) : "f"(f.x), "f"(f.y)); return d;
}

// ---------------- device-global scratch ----------------
// k < 48 : fp32 k-pairs, thread-per-gate coalesced:
//   g_wreg48[((L*24 + (k>>1))*512 + g)*2 + (k&1)]
// k in [48,128): fp16 blocked (8 halves per uint4):
//   g_whh48h[L*40960 + (((k-48)>>3)*512 + g)*8 + ((k-48)&7)]
__device__ float  g_wreg48[2 * 24 * 512 * 2];
__device__ __half g_whh48h[2 * 10 * 512 * 8];
__device__ __half g_wih1h[G4 * HH];               // fp16 blocked, xgate only
__device__ float  g_h1[(size_t)BB * TT * HH];
__device__ float  g_xg1[(size_t)BB * TT * G4];
__device__ float  g_h2last[BB * HH];

__global__ void prep_kernel(const float* __restrict__ w_hh0,
                            const float* __restrict__ w_hh1,
                            const float* __restrict__ w_ih1)
{
    int idx = blockIdx.x * blockDim.x + threadIdx.x;   // 196608 threads
    if (idx < 131072) {
        int L = idx >> 16;
        int e = idx & 65535;
        int g = e >> 7;
        int k = e & 127;
        float v = (L ? w_hh1 : w_hh0)[e];
        if (k < 48) {
            g_wreg48[(((L * 24 + (k >> 1)) * 512 + g) << 1) + (k & 1)] = v;
        } else {
            int kk = k - 48;
            g_whh48h[L * 40960 + (((kk >> 3) * 512 + g) << 3) + (kk & 7)] =
                __float2half(v);
        }
    } else {
        int e = idx - 131072;
        int g = e >> 7;
        int k = e & 127;
        int dst = ((k >> 3) << 12) + (g << 3) + (k & 7);
        g_wih1h[dst] = __float2half(w_ih1[e]);
    }
}

__device__ __forceinline__ float sigf(float x) {
    return 1.0f / (1.0f + __expf(-x));
}
__device__ __forceinline__ float tanhfast(float x) {
    return 2.0f / (1.0f + __expf(-2.0f * x)) - 1.0f;
}

// ---------------- LSTM recurrence ----------------
// 128 CTAs x 2 batch rows, 512 threads (4 warps/SMSP). Thread = gate tid,
// both rows. Register diet: k<48 fp32 in 24 u64 regs; k in [48,128) fp16 smem.
// Target ~100 regs (slack below the 128 cap at 512 threads — the R3/R6/R7
// failure mode was reg-cap exhaustion).
// smem (bytes):
//   [0,81920)        w_hh fp16 blocked (k 48..127), uint4 ws4[c*512+g], c<10
//   [81920,102400)   wih0 fp32 k-major [10][512]   (layer0 only)
//   [102400,104448)  bias [512]                    (layer0 only)
//   [104448,105472)  hs [2 rows][128]
//   [105472,109568)  gs [2 rows][512]
//   [109568,109696)  xs [2 rows][16]               (layer0 only)
#define LSTM_SMEM 109696

template<int LAYER>
__global__ void __launch_bounds__(512, 1) lstm_layer_kernel(
    const float* __restrict__ x,
    const float* __restrict__ w_ih,
    const float* __restrict__ b_ih,
    const float* __restrict__ b_hh)
{
    extern __shared__ char smem[];
    float* ws     = (float*)smem;                    // fp16 region, cast below
    float* wih_s  = (float*)(smem + 81920);
    float* bias_s = (float*)(smem + 102400);
    float* hs     = (float*)(smem + 104448);
    float* gs     = (float*)(smem + 105472);
    float* xs     = (float*)(smem + 109568);

    const int tid = threadIdx.x;        // = gate index
    const int bb  = blockIdx.x;

    // k<48 fp32 weights into 24 u64 registers (coalesced)
    u64 wreg[24];
    {
        const u64* wr = (const u64*)g_wreg48;
        #pragma unroll
        for (int i = 0; i < 24; i++)
            wreg[i] = wr[(LAYER * 24 + i) * 512 + tid];
    }

    // k in [48,128) fp16 weights into smem (10 uint4 per gate)
    uint4* ws4 = (uint4*)ws;
    {
        const uint4* gw4 = (const uint4*)g_whh48h;
        #pragma unroll
        for (int i = 0; i < 10; i++)
            ws4[i * 512 + tid] = gw4[LAYER * 5120 + i * 512 + tid];
    }

    if (LAYER == 0) {
        #pragma unroll
        for (int j = 0; j < IND; j++)
            wih_s[j * 512 + tid] = w_ih[tid * IND + j];
        bias_s[tid] = b_ih[tid] + b_hh[tid];
    }
    if (tid < 256) hs[tid] = 0.0f;

    float creg = 0.0f;                  // cell state: act thread = (row, unit)
    const int r_act = tid >> 7;
    const int j_act = tid & 127;

    // prefetch t=0 step inputs
    float xg0 = 0.0f, xg1v = 0.0f;
    int xr = 0, xj = 0;
    if (LAYER == 0) {
        if (tid < 2 * IND) {
            xr = tid / IND; xj = tid - xr * IND;
            xs[xr * 16 + xj] = x[(size_t)(2 * bb + xr) * (TT * IND) + xj];
        }
    } else {
        xg0  = g_xg1[((size_t)(2 * bb + 0) * TT + 0) * G4 + tid];
        xg1v = g_xg1[((size_t)(2 * bb + 1) * TT + 0) * G4 + tid];
    }
    __syncthreads();

    const ulonglong2* h0v = (const ulonglong2*)hs;          // row0, 4 floats
    const ulonglong2* h1v = (const ulonglong2*)(hs + 128);  // row1

    for (int t = 0; t < TT; t++) {
        // [A] prefetch next step's inputs
        float nx = 0.0f, n0 = 0.0f, n1 = 0.0f;
        if (LAYER == 0) {
            if (tid < 2 * IND && t + 1 < TT)
                nx = x[(size_t)(2 * bb + xr) * (TT * IND) + (size_t)(t + 1) * IND + xj];
        } else {
            if (t + 1 < TT) {
                n0 = g_xg1[((size_t)(2 * bb + 0) * TT + (t + 1)) * G4 + tid];
                n1 = g_xg1[((size_t)(2 * bb + 1) * TT + (t + 1)) * G4 + tid];
            }
        }

        // [B] initial scalar part
        float i0, i1;
        if (LAYER == 0) {
            float bv = bias_s[tid];
            i0 = bv; i1 = bv;
            #pragma unroll
            for (int j = 0; j < IND; j++) {
                float wv = wih_s[j * 512 + tid];
                i0 = fmaf(xs[j],      wv, i0);
                i1 = fmaf(xs[16 + j], wv, i1);
            }
        } else {
            i0 = xg0; i1 = xg1v;
        }

        u64 a0a = pk(i0, 0.0f), a0b = pk(0.0f, 0.0f);
        u64 a1a = pk(i1, 0.0f), a1b = pk(0.0f, 0.0f);

        // k in [0,48): fp32 register weights (12 x 4 k-values)
        #pragma unroll
        for (int i = 0; i < 12; i++) {
            ulonglong2 h0 = h0v[i];
            ulonglong2 h1 = h1v[i];
            ffma2(a0a, h0.x, wreg[2 * i]);
            ffma2(a0b, h0.y, wreg[2 * i + 1]);
            ffma2(a1a, h1.x, wreg[2 * i]);
            ffma2(a1b, h1.y, wreg[2 * i + 1]);
        }

        // k in [48,128): fp16 smem weights (10 x 8 k-values)
        #pragma unroll
        for (int c = 0; c < 10; c++) {
            uint4 wp = ws4[c * 512 + tid];
            u64 w0 = h2u64(wp.x);
            u64 w1 = h2u64(wp.y);
            u64 w2 = h2u64(wp.z);
            u64 w3 = h2u64(wp.w);
            ulonglong2 ha = h0v[12 + 2 * c];
            ulonglong2 hb = h0v[13 + 2 * c];
            ulonglong2 ka = h1v[12 + 2 * c];
            ulonglong2 kb = h1v[13 + 2 * c];
            ffma2(a0a, ha.x, w0); ffma2(a0b, ha.y, w1);
            ffma2(a0a, hb.x, w2); ffma2(a0b, hb.y, w3);
            ffma2(a1a, ka.x, w0); ffma2(a1b, ka.y, w1);
            ffma2(a1a, kb.x, w2); ffma2(a1b, kb.y, w3);
        }

        gs[tid]       = psum(a0a) + psum(a0b);
        gs[512 + tid] = psum(a1a) + psum(a1b);
        __syncthreads();

        // [C] activations + state update (threads 0..255)
        if (tid < 256) {
            const float* gr = gs + r_act * 512;
            float iv = sigf(gr[j_act]);
            float fv = sigf(gr[128 + j_act]);
            float gv = tanhfast(gr[256 + j_act]);
            float ov = sigf(gr[384 + j_act]);
            creg = fv * creg + iv * gv;
            float hn = ov * tanhfast(creg);
            hs[r_act * 128 + j_act] = hn;
            if (LAYER == 0) {
                g_h1[((size_t)(2 * bb + r_act) * TT + t) * HH + j_act] = hn;
            } else if (t == TT - 1) {
                g_h2last[(2 * bb + r_act) * HH + j_act] = hn;
            }
        }
        if (LAYER == 0) {
            if (tid < 2 * IND) xs[xr * 16 + xj] = nx;
        } else {
            xg0 = n0; xg1v = n1;
        }
        __syncthreads();
    }
}

// ---------------- layer-1 input projection GEMM (gate-split, 2 CTAs/SM) ----------------
// CTA = 256 gates x TRG=32 rows; grid 8192. 80KB smem -> 2 resident CTAs/SM
// -> 4 warps/SMSP covers LDS latency. launch_bounds(256,2) caps regs at 128.
#define XG_SMEM (65536 + TRG * HH * 4)

__global__ void __launch_bounds__(256, 2) xgate1_kernel(
    const float* __restrict__ b_ih1, const float* __restrict__ b_hh1)
{
    extern __shared__ char smem[];
    __half* wsm = (__half*)smem;                 // 256 gates x 128 k fp16
    float*  h_s = (float*)(smem + 65536);        // 32 rows x 128

    const int tid   = threadIdx.x;
    const int ghalf = blockIdx.x & 1;
    const int rblk  = blockIdx.x >> 1;
    const int gate  = ghalf * 256 + tid;

    uint4*       wsm4 = (uint4*)wsm;
    const uint4* gw4  = (const uint4*)g_wih1h;
    #pragma unroll
    for (int i = 0; i < 16; i++)
        wsm4[i * 256 + tid] = gw4[i * 512 + gate];

    const size_t base = (size_t)rblk * TRG * HH;
    float4*       h_s4 = (float4*)h_s;
    const float4* src4 = (const float4*)(g_h1 + base);
    #pragma unroll
    for (int i = 0; i < (TRG * HH / 4) / 256; i++)
        h_s4[i * 256 + tid] = src4[i * 256 + tid];
    __syncthreads();

    float bv = b_ih1[gate] + b_hh1[gate];
    u64 acc[TRG];
    #pragma unroll
    for (int r = 0; r < TRG; r++) acc[r] = pk(bv, 0.0f);

    #pragma unroll 1
    for (int c = 0; c < 16; c++) {
        uint4 wp = wsm4[c * 256 + tid];
        u64 w0 = h2u64(wp.x);
        u64 w1 = h2u64(wp.y);
        u64 w2 = h2u64(wp.z);
        u64 w3 = h2u64(wp.w);
        #pragma unroll
        for (int r = 0; r < TRG; r++) {
            ulonglong2 ha = *(const ulonglong2*)(h_s + r * HH + c * 8);
            ulonglong2 hb = *(const ulonglong2*)(h_s + r * HH + c * 8 + 4);
            ffma2(acc[r], ha.x, w0);
            ffma2(acc[r], ha.y, w1);
            ffma2(acc[r], hb.x, w2);
            ffma2(acc[r], hb.y, w3);
        }
    }

    #pragma unroll
    for (int r = 0; r < TRG; r++)
        g_xg1[((size_t)rblk * TRG + r) * G4 + gate] = psum(acc[r]);
}

// ---------------- final FC ----------------
__global__ void fc_kernel(const float* __restrict__ fc_w,
                          const float* __restrict__ fc_b,
                          float* __restrict__ out)
{
    int b = threadIdx.x;
    const float* hrow = g_h2last + b * HH;
    #pragma unroll
    for (int c = 0; c < 10; c++) {
        float acc = fc_b[c];
        #pragma unroll
        for (int k = 0; k < HH; k++)
            acc = fmaf(hrow[k], fc_w[c * HH + k], acc);
        out[b * 10 + c] = acc;
    }
}

extern "C" void kernel_launch(void* const* d_in, const int* in_sizes, int n_in,
                              void* d_out, int out_size)
{
    const float* x     = (const float*)d_in[0];
    const float* w_ih0 = (const float*)d_in[1];
    const float* w_hh0 = (const float*)d_in[2];
    const float* b_ih0 = (const float*)d_in[3];
    const float* b_hh0 = (const float*)d_in[4];
    const float* w_ih1 = (const float*)d_in[5];
    const float* w_hh1 = (const float*)d_in[6];
    const float* b_ih1 = (const float*)d_in[7];
    const float* b_hh1 = (const float*)d_in[8];
    const float* fc_w  = (const float*)d_in[9];
    const float* fc_b  = (const float*)d_in[10];
    float* out = (float*)d_out;

    cudaFuncSetAttribute(lstm_layer_kernel<0>,
                         cudaFuncAttributeMaxDynamicSharedMemorySize, LSTM_SMEM);
    cudaFuncSetAttribute(lstm_layer_kernel<1>,
                         cudaFuncAttributeMaxDynamicSharedMemorySize, LSTM_SMEM);
    cudaFuncSetAttribute(xgate1_kernel,
                         cudaFuncAttributeMaxDynamicSharedMemorySize, XG_SMEM);

    prep_kernel<<<768, 256>>>(w_hh0, w_hh1, w_ih1);
    lstm_layer_kernel<0><<<BB / 2, 512, LSTM_SMEM>>>(x, w_ih0, b_ih0, b_hh0);
    xgate1_kernel<<<(BB * TT / TRG) * 2, 256, XG_SMEM>>>(b_ih1, b_hh1);
    lstm_layer_kernel<1><<<BB / 2, 512, LSTM_SMEM>>>(nullptr, nullptr, nullptr, nullptr);
    fc_kernel<<<1, 256>>>(fc_w, fc_b, out);
}

// round 10
// speedup vs baseline: 1.4282x; 1.4282x over previous
#include <cuda_runtime.h>
#include <cuda_fp16.h>

#define BB   256
#define TT   512
#define HH   128
#define G4   512
#define IND  10
#define TRG  32

typedef unsigned long long u64;

// ---------------- packed f32x2 helpers ----------------
__device__ __forceinline__ void ffma2(u64& acc, u64 a, u64 b) {
    asm("fma.rn.f32x2 %0, %1, %2, %0;" : "+l"(acc) : "l"(a), "l"(b));
}
__device__ __forceinline__ u64 pk(float lo, float hi) {
    u64 d; asm("mov.b64 %0, {%1, %2};" : "=l"(d) : "f"(lo), "f"(hi)); return d;
}
__device__ __forceinline__ float psum(u64 a) {
    float x, y; asm("mov.b64 {%0, %1}, %2;" : "=f"(x), "=f"(y) : "l"(a));
    return x + y;
}
__device__ __forceinline__ u64 h2u64(unsigned int h2bits) {
    __half2 h = *reinterpret_cast<__half2*>(&h2bits);
    float2 f = __half22float2(h);
    u64 d; asm("mov.b64 %0, {%1, %2};" : "=l"(d) : "f"(f.x), "f"(f.y)); return d;
}
__device__ __forceinline__ float tanhapx(float x) {
    float y; asm("tanh.approx.f32 %0, %1;" : "=f"(y) : "f"(x)); return y;
}
__device__ __forceinline__ float sigapx(float x) {
    return fmaf(0.5f, tanhapx(0.5f * x), 0.5f);
}

// ---------------- device-global scratch ----------------
// Pair mapping: gate g -> (slot, thread): slot = (g>>7)&1,
//   t = ((g&127)<<1) | (g>>8).  Thread t owns gA = (t>>1) + (t&1)*256 (slot0)
//   and gB = gA + 128 (slot1): unit u = t>>1; t even -> (i_u,f_u), odd -> (g_u,o_u).
// g_whhph: w_hh fp16, k in [64,128), blocked uint4 (8 halves), pair-indexed:
//   uint4 index = (L*8 + ((k-64)>>3))*512 + slot*256 + t, half slot = (k-64)&7
__device__ __half g_whhph[2 * 8 * 512 * 8];
__device__ __half g_wih1h[G4 * HH];               // fp16 blocked, xgate only
__device__ float  g_h1[(size_t)BB * TT * HH];
__device__ float  g_xg1[(size_t)BB * TT * G4];
__device__ float  g_h2last[BB * HH];

__global__ void prep_kernel(const float* __restrict__ w_hh0,
                            const float* __restrict__ w_hh1,
                            const float* __restrict__ w_ih1)
{
    int idx = blockIdx.x * blockDim.x + threadIdx.x;   // 196608 threads
    if (idx >= 3 * G4 * HH) return;
    int m = idx >> 16;
    int e = idx & 65535;
    int g = e >> 7;
    int k = e & 127;
    if (m < 2) {
        if (k < 64) return;                            // k<64 read from w_hh directly
        int slot = (g >> 7) & 1;
        int t    = ((g & 127) << 1) | (g >> 8);
        float v  = (m ? w_hh1 : w_hh0)[e];
        int kk = k - 64;
        g_whhph[(((m * 8 + (kk >> 3)) * 512 + slot * 256 + t) << 3) + (kk & 7)] =
            __float2half(v);
    } else {
        int dst = ((k >> 3) << 12) + (g << 3) + (k & 7);
        g_wih1h[dst] = __float2half(w_ih1[e]);
    }
}

// ---------------- LSTM recurrence (R4 shape + pairing + 1 barrier) ----------------
// 128 CTAs x 2 batch rows, 256 threads; thread t owns gates gA,gB for both rows.
// k<64: fp32 weights in regs (from w_hh). k in [64,128): fp16 smem, pair-indexed.
// Gate exchange: 4x shfl.xor(1) (partner lane = unit's other gate pair).
// ONE barrier/step; h and x double-buffered; tanh.approx activations.
// smem (bytes):
//   [0,65536)       w_hh fp16 blocked: uint4 ws4[c*512 + slot*256 + t], c<8
//   [65536,86016)   wihp [10][2][256] fp32          (layer0 only)
//   [86016,88064)   biasp [2][256]                  (layer0 only)
//   [88064,90112)   hs [2 buf][2 rows][128]
//   [90112,90368)   xs [2 buf][2 rows][16]          (layer0 only)
#define LSTM_SMEM 90368

template<int LAYER>
__global__ void __launch_bounds__(256, 1) lstm_layer_kernel(
    const float* __restrict__ x,
    const float* __restrict__ w_ih,
    const float* __restrict__ w_hh,
    const float* __restrict__ b_ih,
    const float* __restrict__ b_hh)
{
    extern __shared__ char smem[];
    __half* wsm   = (__half*)smem;
    float*  wihp  = (float*)(smem + 65536);
    float*  biasp = (float*)(smem + 86016);
    float*  hs    = (float*)(smem + 88064);
    float*  xsb   = (float*)(smem + 90112);

    const int tid  = threadIdx.x;
    const int bb   = blockIdx.x;
    const int u    = tid >> 1;
    const int half = tid & 1;
    const int gA   = u + (half ? 256 : 0);
    const int gB   = gA + 128;

    // k<64 fp32 weights for both gates into registers (one-time LDG)
    u64 wreg0[32], wreg1[32];
    {
        const u64* wa = (const u64*)(w_hh + (size_t)gA * HH);
        const u64* wb = (const u64*)(w_hh + (size_t)gB * HH);
        #pragma unroll
        for (int i = 0; i < 32; i++) { wreg0[i] = wa[i]; wreg1[i] = wb[i]; }
    }

    // k in [64,128) fp16 weights into smem (pair-indexed, conflict-free)
    uint4*       ws4 = (uint4*)wsm;
    const uint4* gw4 = (const uint4*)g_whhph;
    #pragma unroll
    for (int i = 0; i < 8; i++) {
        ws4[i * 512 + tid]       = gw4[(LAYER * 8 + i) * 512 + tid];
        ws4[i * 512 + 256 + tid] = gw4[(LAYER * 8 + i) * 512 + 256 + tid];
    }

    if (LAYER == 0) {
        #pragma unroll
        for (int j = 0; j < IND; j++) {
            wihp[(j * 2 + 0) * 256 + tid] = w_ih[gA * IND + j];
            wihp[(j * 2 + 1) * 256 + tid] = w_ih[gB * IND + j];
        }
        biasp[tid]       = b_ih[gA] + b_hh[gA];
        biasp[256 + tid] = b_ih[gB] + b_hh[gB];
    }
    hs[tid] = 0.0f;                     // zero h buffer 0 ([2 rows][128])

    float c0 = 0.0f, c1 = 0.0f;         // unit u cell state, rows 0/1 (pair-redundant)

    // prefetch t=0 step inputs
    float xgA0 = 0.0f, xgA1 = 0.0f, xgB0 = 0.0f, xgB1 = 0.0f;
    int xr = 0, xj = 0;
    if (LAYER == 0) {
        if (tid < 2 * IND) {
            xr = tid / IND; xj = tid - xr * IND;
            xsb[xr * 16 + xj] = x[(size_t)(2 * bb + xr) * (TT * IND) + xj];
        }
    } else {
        const float* p0 = g_xg1 + ((size_t)(2 * bb + 0) * TT + 0) * G4;
        const float* p1 = g_xg1 + ((size_t)(2 * bb + 1) * TT + 0) * G4;
        xgA0 = p0[gA]; xgB0 = p0[gB];
        xgA1 = p1[gA]; xgB1 = p1[gB];
    }
    __syncthreads();

    for (int t = 0; t < TT; t++) {
        const int par = t & 1;
        const ulonglong2* h0v = (const ulonglong2*)(hs + par * 256);
        const ulonglong2* h1v = (const ulonglong2*)(hs + par * 256 + 128);
        float*            nxt = hs + (par ^ 1) * 256;
        const float*      xs  = xsb + par * 32;
        float*            xsn = xsb + (par ^ 1) * 32;

        // [A] prefetch next step's inputs
        float nx = 0.0f, nA0 = 0.0f, nA1 = 0.0f, nB0 = 0.0f, nB1 = 0.0f;
        if (LAYER == 0) {
            if (tid < 2 * IND && t + 1 < TT)
                nx = x[(size_t)(2 * bb + xr) * (TT * IND) + (size_t)(t + 1) * IND + xj];
        } else {
            if (t + 1 < TT) {
                const float* p0 = g_xg1 + ((size_t)(2 * bb + 0) * TT + (t + 1)) * G4;
                const float* p1 = g_xg1 + ((size_t)(2 * bb + 1) * TT + (t + 1)) * G4;
                nA0 = p0[gA]; nB0 = p0[gB];
                nA1 = p1[gA]; nB1 = p1[gB];
            }
        }

        // [B] initial scalar part (bias + x-projection for layer0)
        float iA0, iA1, iB0, iB1;
        if (LAYER == 0) {
            float bvA = biasp[tid], bvB = biasp[256 + tid];
            iA0 = bvA; iA1 = bvA; iB0 = bvB; iB1 = bvB;
            #pragma unroll
            for (int j = 0; j < IND; j++) {
                float wAj = wihp[(j * 2 + 0) * 256 + tid];
                float wBj = wihp[(j * 2 + 1) * 256 + tid];
                float x0 = xs[j], x1 = xs[16 + j];
                iA0 = fmaf(x0, wAj, iA0);
                iA1 = fmaf(x1, wAj, iA1);
                iB0 = fmaf(x0, wBj, iB0);
                iB1 = fmaf(x1, wBj, iB1);
            }
        } else {
            iA0 = xgA0; iA1 = xgA1; iB0 = xgB0; iB1 = xgB1;
        }

        u64 aA0a = pk(iA0, 0.0f), aA0b = pk(0.0f, 0.0f);
        u64 aA1a = pk(iA1, 0.0f), aA1b = pk(0.0f, 0.0f);
        u64 aB0a = pk(iB0, 0.0f), aB0b = pk(0.0f, 0.0f);
        u64 aB1a = pk(iB1, 0.0f), aB1b = pk(0.0f, 0.0f);

        // k in [0,64): fp32 register weights
        #pragma unroll
        for (int i = 0; i < 16; i++) {
            ulonglong2 h0 = h0v[i];
            ulonglong2 h1 = h1v[i];
            ffma2(aA0a, h0.x, wreg0[2 * i]);
            ffma2(aA0b, h0.y, wreg0[2 * i + 1]);
            ffma2(aA1a, h1.x, wreg0[2 * i]);
            ffma2(aA1b, h1.y, wreg0[2 * i + 1]);
            ffma2(aB0a, h0.x, wreg1[2 * i]);
            ffma2(aB0b, h0.y, wreg1[2 * i + 1]);
            ffma2(aB1a, h1.x, wreg1[2 * i]);
            ffma2(aB1b, h1.y, wreg1[2 * i + 1]);
        }

        // k in [64,128): fp16 smem weights (pair-indexed, conflict-free)
        #pragma unroll
        for (int c = 0; c < 8; c++) {
            uint4 wpA = ws4[c * 512 + tid];
            uint4 wpB = ws4[c * 512 + 256 + tid];
            u64 wA0 = h2u64(wpA.x), wA1 = h2u64(wpA.y);
            u64 wA2 = h2u64(wpA.z), wA3 = h2u64(wpA.w);
            u64 wB0 = h2u64(wpB.x), wB1 = h2u64(wpB.y);
            u64 wB2 = h2u64(wpB.z), wB3 = h2u64(wpB.w);
            ulonglong2 ha = h0v[16 + 2 * c];
            ulonglong2 hb = h0v[17 + 2 * c];
            ulonglong2 ka = h1v[16 + 2 * c];
            ulonglong2 kb = h1v[17 + 2 * c];
            ffma2(aA0a, ha.x, wA0); ffma2(aA0b, ha.y, wA1);
            ffma2(aA0a, hb.x, wA2); ffma2(aA0b, hb.y, wA3);
            ffma2(aA1a, ka.x, wA0); ffma2(aA1b, ka.y, wA1);
            ffma2(aA1a, kb.x, wA2); ffma2(aA1b, kb.y, wA3);
            ffma2(aB0a, ha.x, wB0); ffma2(aB0b, ha.y, wB1);
            ffma2(aB0a, hb.x, wB2); ffma2(aB0b, hb.y, wB3);
            ffma2(aB1a, ka.x, wB0); ffma2(aB1b, ka.y, wB1);
            ffma2(aB1a, kb.x, wB2); ffma2(aB1b, kb.y, wB3);
        }

        float vA0 = psum(aA0a) + psum(aA0b);
        float vA1 = psum(aA1a) + psum(aA1b);
        float vB0 = psum(aB0a) + psum(aB0b);
        float vB1 = psum(aB1a) + psum(aB1b);

        // exchange with pair lane: partner holds unit u's other two gates
        float pA0 = __shfl_xor_sync(0xffffffffu, vA0, 1);
        float pA1 = __shfl_xor_sync(0xffffffffu, vA1, 1);
        float pB0 = __shfl_xor_sync(0xffffffffu, vB0, 1);
        float pB1 = __shfl_xor_sync(0xffffffffu, vB1, 1);

        float gi0, gf0, gg0, go0, gi1, gf1, gg1, go1;
        if (half == 0) {      // this thread: (i,f); partner: (g,o)
            gi0 = vA0; gf0 = vB0; gg0 = pA0; go0 = pB0;
            gi1 = vA1; gf1 = vB1; gg1 = pA1; go1 = pB1;
        } else {              // this thread: (g,o); partner: (i,f)
            gi0 = pA0; gf0 = pB0; gg0 = vA0; go0 = vB0;
            gi1 = pA1; gf1 = pB1; gg1 = vA1; go1 = vB1;
        }

        c0 = sigapx(gf0) * c0 + sigapx(gi0) * tanhapx(gg0);
        c1 = sigapx(gf1) * c1 + sigapx(gi1) * tanhapx(gg1);
        float h0n = sigapx(go0) * tanhapx(c0);
        float h1n = sigapx(go1) * tanhapx(c1);

        if (half == 0) nxt[u]       = h0n;
        else           nxt[128 + u] = h1n;

        if (LAYER == 0) {
            g_h1[((size_t)(2 * bb + half) * TT + t) * HH + u] = half ? h1n : h0n;
        } else if (t == TT - 1) {
            g_h2last[(2 * bb + half) * HH + u] = half ? h1n : h0n;
        }

        if (LAYER == 0) {
            if (tid < 2 * IND) xsn[xr * 16 + xj] = nx;
        } else {
            xgA0 = nA0; xgA1 = nA1; xgB0 = nB0; xgB1 = nB1;
        }
        __syncthreads();
    }
}

// ---------------- layer-1 input projection GEMM (EXACT R8 version) ----------------
#define XG_SMEM (131072 + TRG * HH * 4)

__global__ void __launch_bounds__(256, 1) xgate1_kernel(
    const float* __restrict__ b_ih1, const float* __restrict__ b_hh1)
{
    extern __shared__ char smem[];
    __half* wsm = (__half*)smem;
    float*  h_s = (float*)(smem + 131072);

    const int tid = threadIdx.x;
    const int g0t = tid;
    const int g1t = tid + 256;

    uint4*       wsm4 = (uint4*)wsm;
    const uint4* gw4  = (const uint4*)g_wih1h;
    #pragma unroll
    for (int i = 0; i < 16; i++) {
        wsm4[i * 512 + g0t] = gw4[i * 512 + g0t];
        wsm4[i * 512 + g1t] = gw4[i * 512 + g1t];
    }

    const size_t base = (size_t)blockIdx.x * TRG * HH;
    float4*       h_s4 = (float4*)h_s;
    const float4* src4 = (const float4*)(g_h1 + base);
    #pragma unroll
    for (int i = 0; i < (TRG * HH / 4) / 256; i++)
        h_s4[i * 256 + tid] = src4[i * 256 + tid];
    __syncthreads();

    float bvA = b_ih1[g0t] + b_hh1[g0t];
    float bvB = b_ih1[g1t] + b_hh1[g1t];
    u64 accA[TRG], accB[TRG];
    #pragma unroll
    for (int r = 0; r < TRG; r++) { accA[r] = pk(bvA, 0.0f); accB[r] = pk(bvB, 0.0f); }

    #pragma unroll 1
    for (int c = 0; c < 16; c++) {
        uint4 wpA = wsm4[c * 512 + g0t];
        uint4 wpB = wsm4[c * 512 + g1t];
        u64 wA0 = h2u64(wpA.x), wA1 = h2u64(wpA.y);
        u64 wA2 = h2u64(wpA.z), wA3 = h2u64(wpA.w);
        u64 wB0 = h2u64(wpB.x), wB1 = h2u64(wpB.y);
        u64 wB2 = h2u64(wpB.z), wB3 = h2u64(wpB.w);
        #pragma unroll
        for (int r = 0; r < TRG; r++) {
            ulonglong2 ha = *(const ulonglong2*)(h_s + r * HH + c * 8);
            ulonglong2 hb = *(const ulonglong2*)(h_s + r * HH + c * 8 + 4);
            ffma2(accA[r], ha.x, wA0);
            ffma2(accA[r], ha.y, wA1);
            ffma2(accA[r], hb.x, wA2);
            ffma2(accA[r], hb.y, wA3);
            ffma2(accB[r], ha.x, wB0);
            ffma2(accB[r], ha.y, wB1);
            ffma2(accB[r], hb.x, wB2);
            ffma2(accB[r], hb.y, wB3);
        }
    }

    #pragma unroll
    for (int r = 0; r < TRG; r++) {
        g_xg1[((size_t)blockIdx.x * TRG + r) * G4 + g0t] = psum(accA[r]);
        g_xg1[((size_t)blockIdx.x * TRG + r) * G4 + g1t] = psum(accB[r]);
    }
}

// ---------------- final FC ----------------
__global__ void fc_kernel(const float* __restrict__ fc_w,
                          const float* __restrict__ fc_b,
                          float* __restrict__ out)
{
    int b = threadIdx.x;
    const float* hrow = g_h2last + b * HH;
    #pragma unroll
    for (int c = 0; c < 10; c++) {
        float acc = fc_b[c];
        #pragma unroll
        for (int k = 0; k < HH; k++)
            acc = fmaf(hrow[k], fc_w[c * HH + k], acc);
        out[b * 10 + c] = acc;
    }
}

extern "C" void kernel_launch(void* const* d_in, const int* in_sizes, int n_in,
                              void* d_out, int out_size)
{
    const float* x     = (const float*)d_in[0];
    const float* w_ih0 = (const float*)d_in[1];
    const float* w_hh0 = (const float*)d_in[2];
    const float* b_ih0 = (const float*)d_in[3];
    const float* b_hh0 = (const float*)d_in[4];
    const float* w_ih1 = (const float*)d_in[5];
    const float* w_hh1 = (const float*)d_in[6];
    const float* b_ih1 = (const float*)d_in[7];
    const float* b_hh1 = (const float*)d_in[8];
    const float* fc_w  = (const float*)d_in[9];
    const float* fc_b  = (const float*)d_in[10];
    float* out = (float*)d_out;

    cudaFuncSetAttribute(lstm_layer_kernel<0>,
                         cudaFuncAttributeMaxDynamicSharedMemorySize, LSTM_SMEM);
    cudaFuncSetAttribute(lstm_layer_kernel<1>,
                         cudaFuncAttributeMaxDynamicSharedMemorySize, LSTM_SMEM);
    cudaFuncSetAttribute(xgate1_kernel,
                         cudaFuncAttributeMaxDynamicSharedMemorySize, XG_SMEM);

    prep_kernel<<<768, 256>>>(w_hh0, w_hh1, w_ih1);
    lstm_layer_kernel<0><<<BB / 2, 256, LSTM_SMEM>>>(x, w_ih0, w_hh0, b_ih0, b_hh0);
    xgate1_kernel<<<(BB * TT) / TRG, 256, XG_SMEM>>>(b_ih1, b_hh1);
    lstm_layer_kernel<1><<<BB / 2, 256, LSTM_SMEM>>>(nullptr, nullptr, w_hh1, nullptr, nullptr);
    fc_kernel<<<1, 256>>>(fc_w, fc_b, out);
}